// round 10
// baseline (speedup 1.0000x reference)
#include <cuda_runtime.h>
#include <math.h>

// x (32,3,512,512) f32 — single-kernel fused version.
//  branch A: maxpool 3x3 s2 p1 (-inf pad) -> mean -> silu -> gate[ch]
//  branch B: 5x5 s4 p1 zero-pad window sum /25 * gate -> out (128x128)
//
// Warp = 16-row x 256-col strip (8 contiguous cols/lane, two float4/row,
// depth-2 prefetch). Window-sum outputs are buffered in registers; after a
// per-channel inter-block sync (8 blocks/channel, threadfence-reduction
// pattern), each block computes the gate deterministically and scales+stores.

#define NCH 96
#define STRIPS 32     // 512 rows / 16

__device__ float g_partials[NCH * 64];
__device__ int   g_arrive[NCH];
__device__ int   g_done[NCH];

__global__ __launch_bounds__(256, 4) void fused_all_kernel(
    const float* __restrict__ x, float* __restrict__ out)
{
    const int tid  = threadIdx.x;
    const int lane = tid & 31;
    const int warp = tid >> 5;

    // block = 4 strips x 2 halves; grid = 96 * 8
    const int ch   = blockIdx.x >> 3;
    const int grp  = blockIdx.x & 7;
    const int s    = grp * 4 + (warp >> 1);   // strip 0..31 (16 input rows)
    const int h    = warp & 1;                // column half (256 cols)
    const int base = h * 256;

    const float* __restrict__ xc = x + (size_t)ch * 262144;
    const float* __restrict__ rp = xc + base + lane * 8;   // lane's 8-col segment
    const float* __restrict__ hp = xc + 255;               // halo col (h==1 only)
    const int r0 = 16 * s - 1;                             // row of q=0

    float wsa0=0.f, wsa1=0.f, wsa2=0.f, wsa3=0.f;
    float wsb0=0.f, wsb1=0.f, wsb2=0.f, wsb3=0.f;
    float wma0=-INFINITY, wma1=-INFINITY, wma2=-INFINITY, wma3=-INFINITY;
    float wmb0=-INFINITY, wmb1=-INFINITY, wmb2=-INFINITY, wmb3=-INFINITY;
    float hsum = 0.f, hmax = -INFINITY;
    float lsum = 0.f;
    float2 ob[4];                              // buffered window-sum outputs

    const bool do_halo = (lane == 0) && (h == 1);

    // prime q=0 (row 16s-1; pad row when s==0)
    float4 curA, curB; float hcur;
    if (s > 0) {
        curA = *(const float4*)(rp + (size_t)r0 * 512);
        curB = *(const float4*)(rp + (size_t)r0 * 512 + 4);
        hcur = do_halo ? hp[(size_t)r0 * 512] : 0.f;
    } else {
        curA = make_float4(0.f, 0.f, 0.f, 0.f);
        curB = curA;
        hcur = 0.f;
    }

    #pragma unroll
    for (int q = 0; q <= 16; ++q) {
        float4 nxtA, nxtB; float hnxt = 0.f;
        if (q < 16) {
            const size_t ro = (size_t)(r0 + q + 1) * 512;
            nxtA = *(const float4*)(rp + ro);
            nxtB = *(const float4*)(rp + ro + 4);
            if (do_halo) hnxt = hp[ro];
        }

        // window sums (zero pad: always add)
        wsa0 += curA.x; wsa1 += curA.y; wsa2 += curA.z; wsa3 += curA.w;
        wsb0 += curB.x; wsb1 += curB.y; wsb2 += curB.z; wsb3 += curB.w;
        hsum += hcur;
        // max (exclude the -inf pad row at s==0,q==0)
        if (q > 0 || s > 0) {
            wma0 = fmaxf(wma0, curA.x); wma1 = fmaxf(wma1, curA.y);
            wma2 = fmaxf(wma2, curA.z); wma3 = fmaxf(wma3, curA.w);
            wmb0 = fmaxf(wmb0, curB.x); wmb1 = fmaxf(wmb1, curB.y);
            wmb2 = fmaxf(wmb2, curB.z); wmb3 = fmaxf(wmb3, curB.w);
            if (h == 1) hmax = fmaxf(hmax, hcur);
        }

        // finalize maxpool row at even q >= 2
        if (q >= 2 && (q & 1) == 0) {
            float left = __shfl_up_sync(0xffffffffu, wmb3, 1);
            if (lane == 0) left = (h == 1) ? hmax : -INFINITY;
            float m0 = fmaxf(fmaxf(left, wma0), wma1);
            float m1 = fmaxf(fmaxf(wma1, wma2), wma3);
            float m2 = fmaxf(fmaxf(wma3, wmb0), wmb1);
            float m3 = fmaxf(fmaxf(wmb1, wmb2), wmb3);
            lsum += (m0 + m1) + (m2 + m3);
            if (q < 16) {
                wma0 = curA.x; wma1 = curA.y; wma2 = curA.z; wma3 = curA.w;
                wmb0 = curB.x; wmb1 = curB.y; wmb2 = curB.z; wmb3 = curB.w;
                hmax = (h == 1) ? hcur : -INFINITY;
            }
        }

        // finalize window row oy = 4s + q/4 - 1 at q = 4,8,12,16 -> buffer
        if (q >= 4 && (q & 3) == 0) {
            float left = __shfl_up_sync(0xffffffffu, wsb3, 1);
            if (lane == 0) left = (h == 1) ? hsum : 0.f;
            float w0 = left + wsa0 + wsa1 + wsa2 + wsa3;
            float w1 = wsa3 + wsb0 + wsb1 + wsb2 + wsb3;
            ob[(q >> 2) - 1] = make_float2(w0, w1);
            if (q < 16) {
                wsa0 = curA.x; wsa1 = curA.y; wsa2 = curA.z; wsa3 = curA.w;
                wsb0 = curB.x; wsb1 = curB.y; wsb2 = curB.z; wsb3 = curB.w;
                hsum = hcur;
            }
        }

        curA = nxtA; curB = nxtB; hcur = hnxt;
    }

    // ---- publish gate partial (one per warp: 64 per channel) ----
    #pragma unroll
    for (int o = 16; o > 0; o >>= 1)
        lsum += __shfl_down_sync(0xffffffffu, lsum, o);
    if (lane == 0) {
        g_partials[ch * 64 + s * 2 + h] = lsum;
        __threadfence();
    }
    __syncthreads();

    // ---- per-channel inter-block sync + gate (deterministic) ----
    __shared__ float gsh;
    if (tid == 0) {
        __threadfence();
        atomicAdd(&g_arrive[ch], 1);
        while (*(volatile int*)&g_arrive[ch] < 8) __nanosleep(64);
        __threadfence();
        float ssum = 0.f;
        #pragma unroll 8
        for (int i = 0; i < 64; ++i) ssum += g_partials[ch * 64 + i];
        float m = ssum * (1.0f / 65536.0f);           // mean over 256x256 pooled
        gsh = (m / (1.0f + expf(-m))) * (1.0f / 25.0f);
        int d = atomicAdd(&g_done[ch], 1);
        if (d == 7) {                                 // last block resets for replay
            atomicExch(&g_arrive[ch], 0);
            atomicExch(&g_done[ch], 0);
        }
    }
    __syncthreads();
    const float g = gsh;

    // ---- scale + store buffered outputs ----
    const int ox = h * 64 + lane * 2;
    float* op = &out[((size_t)ch * 128 + 4 * s) * 128 + ox];
    #pragma unroll
    for (int i = 0; i < 4; ++i) {
        float2 v = ob[i];
        v.x *= g; v.y *= g;
        *(float2*)(op + (size_t)i * 128) = v;
    }
}

extern "C" void kernel_launch(void* const* d_in, const int* in_sizes, int n_in,
                              void* d_out, int out_size)
{
    const float* x = (const float*)d_in[0];
    float* out = (float*)d_out;

    fused_all_kernel<<<NCH * 8, 256>>>(x, out);
}

// round 14
// speedup vs baseline: 1.0581x; 1.0581x over previous
#include <cuda_runtime.h>
#include <math.h>

// x (32,3,512,512) f32 — single-kernel, cluster-per-channel version.
//  branch A: maxpool 3x3 s2 p1 (-inf pad) -> mean -> silu -> gate[ch]
//  branch B: 5x5 s4 p1 zero-pad window sum /25 * gate -> out (128x128)
//
// Cluster of 8 CTAs = one channel (HW-guaranteed co-residency -> no spin).
// Warp = 16-row x 256-col strip (8 cols/lane, two float4/row, depth-2
// prefetch). Window-sum outputs buffered in registers. Gate partials shared
// via DSMEM after barrier.cluster; every CTA reduces the same 64 values in
// the same order (deterministic), then scales+stores its buffered rows.

#define NCH 96

__device__ __forceinline__ float dsmem_read_f32(unsigned local_addr, unsigned rank)
{
    unsigned remote;
    asm volatile("mapa.shared::cluster.u32 %0, %1, %2;"
                 : "=r"(remote) : "r"(local_addr), "r"(rank));
    float v;
    asm volatile("ld.shared::cluster.f32 %0, [%1];" : "=f"(v) : "r"(remote));
    return v;
}

__global__ __launch_bounds__(256, 4) __cluster_dims__(8, 1, 1)
void fused_cluster_kernel(const float* __restrict__ x, float* __restrict__ out)
{
    __shared__ float part[8];
    __shared__ float gsh;

    const int tid  = threadIdx.x;
    const int lane = tid & 31;
    const int warp = tid >> 5;

    const int ch   = blockIdx.x >> 3;         // cluster id = channel
    const int rank = blockIdx.x & 7;          // CTA rank within cluster
    const int s    = rank * 4 + (warp >> 1);  // strip 0..31 (16 input rows)
    const int h    = warp & 1;                // column half (256 cols)
    const int base = h * 256;

    const float* __restrict__ xc = x + (size_t)ch * 262144;
    const float* __restrict__ rp = xc + base + lane * 8;   // lane's 8-col segment
    const float* __restrict__ hp = xc + 255;               // halo col (h==1 only)
    const int r0 = 16 * s - 1;                             // row of q=0

    float wsa0=0.f, wsa1=0.f, wsa2=0.f, wsa3=0.f;
    float wsb0=0.f, wsb1=0.f, wsb2=0.f, wsb3=0.f;
    float wma0=-INFINITY, wma1=-INFINITY, wma2=-INFINITY, wma3=-INFINITY;
    float wmb0=-INFINITY, wmb1=-INFINITY, wmb2=-INFINITY, wmb3=-INFINITY;
    float hsum = 0.f, hmax = -INFINITY;
    float lsum = 0.f;
    float2 ob[4];                              // buffered window-sum outputs

    const bool do_halo = (lane == 0) && (h == 1);

    // prime q=0 (row 16s-1; pad row when s==0)
    float4 curA, curB; float hcur;
    if (s > 0) {
        curA = *(const float4*)(rp + (size_t)r0 * 512);
        curB = *(const float4*)(rp + (size_t)r0 * 512 + 4);
        hcur = do_halo ? hp[(size_t)r0 * 512] : 0.f;
    } else {
        curA = make_float4(0.f, 0.f, 0.f, 0.f);
        curB = curA;
        hcur = 0.f;
    }

    #pragma unroll
    for (int q = 0; q <= 16; ++q) {
        float4 nxtA, nxtB; float hnxt = 0.f;
        if (q < 16) {
            const size_t ro = (size_t)(r0 + q + 1) * 512;
            nxtA = *(const float4*)(rp + ro);
            nxtB = *(const float4*)(rp + ro + 4);
            if (do_halo) hnxt = hp[ro];
        }

        // window sums (zero pad: always add)
        wsa0 += curA.x; wsa1 += curA.y; wsa2 += curA.z; wsa3 += curA.w;
        wsb0 += curB.x; wsb1 += curB.y; wsb2 += curB.z; wsb3 += curB.w;
        hsum += hcur;
        // max (exclude the -inf pad row at s==0,q==0)
        if (q > 0 || s > 0) {
            wma0 = fmaxf(wma0, curA.x); wma1 = fmaxf(wma1, curA.y);
            wma2 = fmaxf(wma2, curA.z); wma3 = fmaxf(wma3, curA.w);
            wmb0 = fmaxf(wmb0, curB.x); wmb1 = fmaxf(wmb1, curB.y);
            wmb2 = fmaxf(wmb2, curB.z); wmb3 = fmaxf(wmb3, curB.w);
            if (h == 1) hmax = fmaxf(hmax, hcur);
        }

        // finalize maxpool row at even q >= 2
        if (q >= 2 && (q & 1) == 0) {
            float left = __shfl_up_sync(0xffffffffu, wmb3, 1);
            if (lane == 0) left = (h == 1) ? hmax : -INFINITY;
            float m0 = fmaxf(fmaxf(left, wma0), wma1);
            float m1 = fmaxf(fmaxf(wma1, wma2), wma3);
            float m2 = fmaxf(fmaxf(wma3, wmb0), wmb1);
            float m3 = fmaxf(fmaxf(wmb1, wmb2), wmb3);
            lsum += (m0 + m1) + (m2 + m3);
            if (q < 16) {
                wma0 = curA.x; wma1 = curA.y; wma2 = curA.z; wma3 = curA.w;
                wmb0 = curB.x; wmb1 = curB.y; wmb2 = curB.z; wmb3 = curB.w;
                hmax = (h == 1) ? hcur : -INFINITY;
            }
        }

        // finalize window row oy = 4s + q/4 - 1 at q = 4,8,12,16 -> buffer
        if (q >= 4 && (q & 3) == 0) {
            float left = __shfl_up_sync(0xffffffffu, wsb3, 1);
            if (lane == 0) left = (h == 1) ? hsum : 0.f;
            float w0 = left + wsa0 + wsa1 + wsa2 + wsa3;
            float w1 = wsa3 + wsb0 + wsb1 + wsb2 + wsb3;
            ob[(q >> 2) - 1] = make_float2(w0, w1);
            if (q < 16) {
                wsa0 = curA.x; wsa1 = curA.y; wsa2 = curA.z; wsa3 = curA.w;
                wsb0 = curB.x; wsb1 = curB.y; wsb2 = curB.z; wsb3 = curB.w;
                hsum = hcur;
            }
        }

        curA = nxtA; curB = nxtB; hcur = hnxt;
    }

    // ---- per-warp gate partial -> CTA smem ----
    #pragma unroll
    for (int o = 16; o > 0; o >>= 1)
        lsum += __shfl_down_sync(0xffffffffu, lsum, o);
    if (lane == 0) part[warp] = lsum;
    __syncthreads();

    // ---- cluster barrier: all 64 partials of the channel are published ----
    asm volatile("barrier.cluster.arrive.aligned;" ::: "memory");
    asm volatile("barrier.cluster.wait.aligned;"   ::: "memory");

    // ---- every CTA gathers all 8x8 partials via DSMEM, reduces (fixed order) ----
    if (warp == 0) {
        unsigned pa;
        {
            unsigned long long t;
            asm("{ .reg .u64 a; cvta.to.shared.u64 a, %1; mov.u64 %0, a; }"
                : "=l"(t) : "l"((const void*)part));
            pa = (unsigned)t;
        }
        float v0 = dsmem_read_f32(pa + (lane & 7) * 4, (unsigned)(lane >> 3));
        float v1 = dsmem_read_f32(pa + (lane & 7) * 4, (unsigned)(4 + (lane >> 3)));
        float v = v0 + v1;
        #pragma unroll
        for (int o = 16; o > 0; o >>= 1)
            v += __shfl_down_sync(0xffffffffu, v, o);
        if (lane == 0) {
            float m = v * (1.0f / 65536.0f);          // mean over 256x256 pooled
            gsh = (m / (1.0f + expf(-m))) * (1.0f / 25.0f);
        }
    }
    __syncthreads();
    const float g = gsh;

    // ---- scale + store buffered outputs ----
    const int ox = h * 64 + lane * 2;
    float* op = &out[((size_t)ch * 128 + 4 * s) * 128 + ox];
    #pragma unroll
    for (int i = 0; i < 4; ++i) {
        float2 v = ob[i];
        v.x *= g; v.y *= g;
        *(float2*)(op + (size_t)i * 128) = v;
    }

    // ---- keep smem alive until all peers have gathered ----
    asm volatile("barrier.cluster.arrive.aligned;" ::: "memory");
    asm volatile("barrier.cluster.wait.aligned;"   ::: "memory");
}

extern "C" void kernel_launch(void* const* d_in, const int* in_sizes, int n_in,
                              void* d_out, int out_size)
{
    const float* x = (const float*)d_in[0];
    float* out = (float*)d_out;

    fused_cluster_kernel<<<NCH * 8, 256>>>(x, out);
}

// round 17
// speedup vs baseline: 1.1013x; 1.0408x over previous
#include <cuda_runtime.h>
#include <math.h>

// x (32,3,512,512) f32 — single-kernel, cluster-per-channel, no register buffer.
//  branch A: maxpool 3x3 s2 p1 (-inf pad) -> mean -> silu -> gate[ch]
//  branch B: 5x5 s4 p1 zero-pad window sum /25 * gate -> out (128x128)
//
// Loop identical to the 18.9us two-kernel version: warp = 16-row x 256-col
// strip, unscaled window sums stored to gmem immediately (no live buffer).
// Then: cluster barrier -> DSMEM gather of 64 gate partials (fixed order,
// deterministic) -> each thread re-reads its own 8 floats from L2, scales,
// rewrites. Same-thread STG->LDG needs no fence.

#define NCH 96

__device__ __forceinline__ float dsmem_read_f32(unsigned local_addr, unsigned rank)
{
    unsigned remote;
    asm volatile("mapa.shared::cluster.u32 %0, %1, %2;"
                 : "=r"(remote) : "r"(local_addr), "r"(rank));
    float v;
    asm volatile("ld.shared::cluster.f32 %0, [%1];" : "=f"(v) : "r"(remote));
    return v;
}

__global__ __launch_bounds__(256, 4) __cluster_dims__(8, 1, 1)
void fused_cluster_kernel(const float* __restrict__ x, float* __restrict__ out)
{
    __shared__ float part[8];
    __shared__ float gsh;

    const int tid  = threadIdx.x;
    const int lane = tid & 31;
    const int warp = tid >> 5;

    const int ch   = blockIdx.x >> 3;         // cluster id = channel
    const int rank = blockIdx.x & 7;          // CTA rank within cluster
    const int s    = rank * 4 + (warp >> 1);  // strip 0..31 (16 input rows)
    const int h    = warp & 1;                // column half (256 cols)
    const int base = h * 256;

    const float* __restrict__ xc = x + (size_t)ch * 262144;
    const float* __restrict__ rp = xc + base + lane * 8;   // lane's 8-col segment
    const float* __restrict__ hp = xc + 255;               // halo col (h==1 only)
    const int r0 = 16 * s - 1;                             // row of q=0

    const int ox = h * 64 + lane * 2;
    float* const op = &out[((size_t)ch * 128 + 4 * s) * 128 + ox];

    float wsa0=0.f, wsa1=0.f, wsa2=0.f, wsa3=0.f;
    float wsb0=0.f, wsb1=0.f, wsb2=0.f, wsb3=0.f;
    float wma0=-INFINITY, wma1=-INFINITY, wma2=-INFINITY, wma3=-INFINITY;
    float wmb0=-INFINITY, wmb1=-INFINITY, wmb2=-INFINITY, wmb3=-INFINITY;
    float hsum = 0.f, hmax = -INFINITY;
    float lsum = 0.f;

    const bool do_halo = (lane == 0) && (h == 1);

    // prime q=0 (row 16s-1; pad row when s==0)
    float4 curA, curB; float hcur;
    if (s > 0) {
        curA = *(const float4*)(rp + (size_t)r0 * 512);
        curB = *(const float4*)(rp + (size_t)r0 * 512 + 4);
        hcur = do_halo ? hp[(size_t)r0 * 512] : 0.f;
    } else {
        curA = make_float4(0.f, 0.f, 0.f, 0.f);
        curB = curA;
        hcur = 0.f;
    }

    #pragma unroll
    for (int q = 0; q <= 16; ++q) {
        float4 nxtA, nxtB; float hnxt = 0.f;
        if (q < 16) {
            const size_t ro = (size_t)(r0 + q + 1) * 512;
            nxtA = *(const float4*)(rp + ro);
            nxtB = *(const float4*)(rp + ro + 4);
            if (do_halo) hnxt = hp[ro];
        }

        // window sums (zero pad: always add)
        wsa0 += curA.x; wsa1 += curA.y; wsa2 += curA.z; wsa3 += curA.w;
        wsb0 += curB.x; wsb1 += curB.y; wsb2 += curB.z; wsb3 += curB.w;
        hsum += hcur;
        // max (exclude the -inf pad row at s==0,q==0)
        if (q > 0 || s > 0) {
            wma0 = fmaxf(wma0, curA.x); wma1 = fmaxf(wma1, curA.y);
            wma2 = fmaxf(wma2, curA.z); wma3 = fmaxf(wma3, curA.w);
            wmb0 = fmaxf(wmb0, curB.x); wmb1 = fmaxf(wmb1, curB.y);
            wmb2 = fmaxf(wmb2, curB.z); wmb3 = fmaxf(wmb3, curB.w);
            if (h == 1) hmax = fmaxf(hmax, hcur);
        }

        // finalize maxpool row at even q >= 2
        if (q >= 2 && (q & 1) == 0) {
            float left = __shfl_up_sync(0xffffffffu, wmb3, 1);
            if (lane == 0) left = (h == 1) ? hmax : -INFINITY;
            float m0 = fmaxf(fmaxf(left, wma0), wma1);
            float m1 = fmaxf(fmaxf(wma1, wma2), wma3);
            float m2 = fmaxf(fmaxf(wma3, wmb0), wmb1);
            float m3 = fmaxf(fmaxf(wmb1, wmb2), wmb3);
            lsum += (m0 + m1) + (m2 + m3);
            if (q < 16) {
                wma0 = curA.x; wma1 = curA.y; wma2 = curA.z; wma3 = curA.w;
                wmb0 = curB.x; wmb1 = curB.y; wmb2 = curB.z; wmb3 = curB.w;
                hmax = (h == 1) ? hcur : -INFINITY;
            }
        }

        // finalize window row oy = 4s + q/4 - 1 at q = 4,8,12,16 -> store unscaled
        if (q >= 4 && (q & 3) == 0) {
            float left = __shfl_up_sync(0xffffffffu, wsb3, 1);
            if (lane == 0) left = (h == 1) ? hsum : 0.f;
            float w0 = left + wsa0 + wsa1 + wsa2 + wsa3;
            float w1 = wsa3 + wsb0 + wsb1 + wsb2 + wsb3;
            *(float2*)(op + (size_t)((q >> 2) - 1) * 128) = make_float2(w0, w1);
            if (q < 16) {
                wsa0 = curA.x; wsa1 = curA.y; wsa2 = curA.z; wsa3 = curA.w;
                wsb0 = curB.x; wsb1 = curB.y; wsb2 = curB.z; wsb3 = curB.w;
                hsum = hcur;
            }
        }

        curA = nxtA; curB = nxtB; hcur = hnxt;
    }

    // ---- per-warp gate partial -> CTA smem ----
    #pragma unroll
    for (int o = 16; o > 0; o >>= 1)
        lsum += __shfl_down_sync(0xffffffffu, lsum, o);
    if (lane == 0) part[warp] = lsum;
    __syncthreads();

    // ---- cluster barrier: all 64 partials of the channel are published ----
    asm volatile("barrier.cluster.arrive.aligned;" ::: "memory");
    asm volatile("barrier.cluster.wait.aligned;"   ::: "memory");

    // ---- every CTA gathers all 8x8 partials via DSMEM, reduces (fixed order) ----
    if (warp == 0) {
        unsigned pa;
        {
            unsigned long long t;
            asm("{ .reg .u64 a; cvta.to.shared.u64 a, %1; mov.u64 %0, a; }"
                : "=l"(t) : "l"((const void*)part));
            pa = (unsigned)t;
        }
        float v0 = dsmem_read_f32(pa + (lane & 7) * 4, (unsigned)(lane >> 3));
        float v1 = dsmem_read_f32(pa + (lane & 7) * 4, (unsigned)(4 + (lane >> 3)));
        float v = v0 + v1;
        #pragma unroll
        for (int o = 16; o > 0; o >>= 1)
            v += __shfl_down_sync(0xffffffffu, v, o);
        if (lane == 0) {
            float m = v * (1.0f / 65536.0f);          // mean over 256x256 pooled
            gsh = (m / (1.0f + expf(-m))) * (1.0f / 25.0f);
        }
    }
    __syncthreads();
    const float g = gsh;

    // ---- rescale own outputs (same-thread STG->LDG: L2 hits, no fence needed) ----
    #pragma unroll
    for (int i = 0; i < 4; ++i) {
        float2 v = *(float2*)(op + (size_t)i * 128);
        v.x *= g; v.y *= g;
        *(float2*)(op + (size_t)i * 128) = v;
    }

    // ---- keep smem alive until all peers have gathered ----
    asm volatile("barrier.cluster.arrive.aligned;" ::: "memory");
    asm volatile("barrier.cluster.wait.aligned;"   ::: "memory");
}

extern "C" void kernel_launch(void* const* d_in, const int* in_sizes, int n_in,
                              void* d_out, int out_size)
{
    const float* x = (const float*)d_in[0];
    float* out = (float*)d_out;

    fused_cluster_kernel<<<NCH * 8, 256>>>(x, out);
}